// round 15
// baseline (speedup 1.0000x reference)
#include <cuda_runtime.h>
#include <cuda_fp16.h>
#include <cstdint>

#define TT   2048
#define HH   2048
#define II   1024
#define EE   16
#define TOPK 4

// ---------------- PTX helpers (sm_80-level only; target is plain sm_103) -------
__device__ __forceinline__ uint32_t smem_to_u32(const void* p) {
    uint32_t a;
    asm("{ .reg .u64 t; cvta.to.shared.u64 t, %1; cvt.u32.u64 %0, t; }"
        : "=r"(a) : "l"(p));
    return a;
}
#define CP_ASYNC16(dst, src) \
    asm volatile("cp.async.cg.shared.global [%0], [%1], 16;" :: "r"(dst), "l"(src) : "memory")
#define CP_ASYNC16Z(dst, src, ssz) \
    asm volatile("cp.async.cg.shared.global [%0], [%1], 16, %2;" :: "r"(dst), "l"(src), "r"(ssz) : "memory")
#define CP_COMMIT()  asm volatile("cp.async.commit_group;" ::: "memory")
#define CP_WAIT(n)   asm volatile("cp.async.wait_group %0;" :: "n"(n) : "memory")

#define LDSM_X4(r0, r1, r2, r3, addr) \
    asm volatile("ldmatrix.sync.aligned.m8n8.x4.shared.b16 {%0,%1,%2,%3}, [%4];" \
                 : "=r"(r0), "=r"(r1), "=r"(r2), "=r"(r3) : "r"(addr))

// D += A*B  (m16n8k16, fp16 in, f32 accum)
__device__ __forceinline__ void mma16816(float* c, const uint32_t* a, const uint32_t* b) {
    asm volatile(
        "mma.sync.aligned.m16n8k16.row.col.f32.f16.f16.f32 "
        "{%0,%1,%2,%3}, {%4,%5,%6,%7}, {%8,%9}, {%0,%1,%2,%3};"
        : "+f"(c[0]), "+f"(c[1]), "+f"(c[2]), "+f"(c[3])
        : "r"(a[0]), "r"(a[1]), "r"(a[2]), "r"(a[3]), "r"(b[0]), "r"(b[1]));
}

// ---------------- scratch ----------------
__device__ int   g_counts[EE];
__device__ int   g_tok[EE * TT];
__device__ int   g_tslot[TT * TOPK];
__device__ float g_twt[TT * TOPK];
__device__ __half g_h2h [(size_t)EE * TT * HH];       // down-proj result fp16
__device__ __half g_hsf [(size_t)TT * HH];            // hs fp16
__device__ __half g_actf[(size_t)EE * TT * II];       // act fp16
__device__ __half g_w13f[(size_t)EE * 2 * II * HH];   // [e*2+mat][i][h] fp16
__device__ __half g_w2f [(size_t)EE * HH * II];       // [e][h][i] fp16

__device__ __forceinline__ uint32_t pack2h(__half a, __half b) {
    return (uint32_t)__half_as_ushort(a) | ((uint32_t)__half_as_ushort(b) << 16);
}

// ---------------- router (+ fused hs->fp16 + fused w13 prep tail) --------------
__global__ void zero_counts_kernel() {
    if (threadIdx.x < EE) g_counts[threadIdx.x] = 0;
}

__global__ void router_kernel(const float* __restrict__ hs,
                              const float* __restrict__ gw,
                              const float* __restrict__ w1,
                              const float* __restrict__ w3) {
    const int t = blockIdx.x;
    __shared__ float xs[HH];
    __shared__ float logits[EE];
    __shared__ __half ts[32 * 66];         // w13 transpose stage
    const float* x = hs + (size_t)t * HH;
    for (int i = threadIdx.x; i < HH; i += blockDim.x) xs[i] = x[i];
    __syncthreads();
    {
        uint32_t* dst = (uint32_t*)(g_hsf + (size_t)t * HH);
        for (int i = threadIdx.x; i < HH / 2; i += blockDim.x)
            dst[i] = pack2h(__float2half_rn(xs[2 * i]), __float2half_rn(xs[2 * i + 1]));
    }
    const int warp = threadIdx.x >> 5, lane = threadIdx.x & 31;
    for (int e = warp; e < EE; e += 8) {
        const float* g = gw + (size_t)e * HH;
        float s = 0.f;
        for (int k = lane; k < HH; k += 32) s += xs[k] * g[k];
        #pragma unroll
        for (int o = 16; o; o >>= 1) s += __shfl_xor_sync(0xffffffffu, s, o);
        if (lane == 0) logits[e] = s;
    }
    __syncthreads();
    if (threadIdx.x == 0) {
        float lv[EE];
        #pragma unroll
        for (int e = 0; e < EE; e++) lv[e] = logits[e];
        int idx[TOPK]; float val[TOPK];
        #pragma unroll
        for (int k = 0; k < TOPK; k++) {
            float best = -1e30f; int bi = 0;
            for (int e = 0; e < EE; e++) if (lv[e] > best) { best = lv[e]; bi = e; }
            idx[k] = bi; val[k] = best; lv[bi] = -1e30f;
        }
        const float m = val[0];
        float w[TOPK], se = 0.f;
        #pragma unroll
        for (int k = 0; k < TOPK; k++) { w[k] = __expf(val[k] - m); se += w[k]; }
        const float inv = 1.f / se;
        #pragma unroll
        for (int k = 0; k < TOPK; k++) {
            const int e = idx[k];
            const int slot = atomicAdd(&g_counts[e], 1);
            g_tok[e * TT + slot]  = t;
            g_tslot[t * TOPK + k] = e * TT + slot;
            g_twt[t * TOPK + k]   = w[k] * inv;
        }
    }
    // fused w13 prepass tail: 16 transpose tiles per block
    {
        const int tx = threadIdx.x & 31, ty = threadIdx.x >> 5;  // (32, 8)
        #pragma unroll 1
        for (int tt = 0; tt < 16; tt++) {
            const int tile = blockIdx.x * 16 + tt;
            const int z    = tile >> 10;
            const int rem  = tile & 1023;
            const int i0   = (rem >> 5) * 32;
            const int h0   = (rem & 31) * 64;
            const float* src = (z & 1 ? w3 : w1) + (size_t)(z >> 1) * HH * II;
            __syncthreads();
            #pragma unroll
            for (int j = 0; j < 8; j++) {
                const int h = ty + 8 * j;
                ts[tx * 66 + h] = __float2half_rn(src[(size_t)(h0 + h) * II + i0 + tx]);
            }
            __syncthreads();
            #pragma unroll
            for (int j = 0; j < 4; j++) {
                const int i = ty + 8 * j;
                const uint32_t v = *(const uint32_t*)&ts[i * 66 + 2 * tx];
                *(uint32_t*)(g_w13f + ((size_t)z * II + i0 + i) * HH + h0 + 2 * tx) = v;
            }
        }
    }
}

// ---------------- gemm13: 512thr, block 256m x (64n x2 mats), warp 32x32x2 -----
#define STRIDE_H 40
#define G13_AB   (256 * STRIDE_H * 2)      // 20480 A tile (256 x 32k)
#define G13_BB   (64 * STRIDE_H * 2)       // 5120 per B plane
#define G13_BUF  (G13_AB + 2 * G13_BB)     // 30720 per buffer
#define G13_SMEM (3 * G13_BUF + 1024)      // 93184

__global__ __launch_bounds__(512, 1)
void gemm13_wm(const float* __restrict__ w2) {
    extern __shared__ char smem[];
    const int e    = blockIdx.z;
    const int cnt  = g_counts[e];
    const int m0b  = blockIdx.y * 256;
    const int n0b  = blockIdx.x * 64;

    const int tid  = threadIdx.x;
    const int wid  = tid >> 5, lane = tid & 31;
    const int m0w  = (wid & 7) * 32;       // 8 m-warps
    const int n0w  = (wid >> 3) * 32;      // 2 n-warps
    const uint32_t sb = smem_to_u32(smem);

    if (m0b < cnt) {
        int* rowTokS = (int*)(smem + 3 * G13_BUF);
        if (tid < 256) rowTokS[tid] = (m0b + tid < cnt) ? g_tok[e * TT + m0b + tid] : -1;
        __syncthreads();

        const __half* srcB1 = g_w13f + ((size_t)(e * 2 + 0) * II + n0b) * HH;
        const __half* srcB3 = g_w13f + ((size_t)(e * 2 + 1) * II + n0b) * HH;

        float acc1[2][4][4], acc3[2][4][4];
        #pragma unroll
        for (int mt = 0; mt < 2; mt++)
            #pragma unroll
            for (int nt = 0; nt < 4; nt++)
                #pragma unroll
                for (int j = 0; j < 4; j++) { acc1[mt][nt][j] = 0.f; acc3[mt][nt][j] = 0.f; }

        const uint32_t aRowOff = (uint32_t)((lane & 15) * 80 + ((lane >> 4) & 1) * 16);
        const uint32_t bRowOff = (uint32_t)((((lane >> 4) & 1) * 8 + (lane & 7)) * 80 +
                                            ((lane >> 3) & 1) * 16);

        auto load_chunk = [&](int buf, int c) {
            const int k0 = c * 32;
            const uint32_t base = sb + buf * G13_BUF;
            // A: 256 rows x 4 segs = 1024 ops, 2 passes of 512
            #pragma unroll
            for (int it = 0; it < 2; it++) {
                const int idx = tid + it * 512;
                const int row = idx >> 2, seg = idx & 3;
                const int tok = rowTokS[row];
                const uint32_t dst = base + row * 80 + seg * 16;
                const __half* s =
                    (tok >= 0 ? g_hsf + (size_t)tok * HH : g_hsf) + k0 + seg * 8;
                const uint32_t ssz = (tok >= 0) ? 16u : 0u;
                CP_ASYNC16Z(dst, s, ssz);
            }
            // B: 2 planes x 64 rows x 4 segs = 512 ops, 1 pass
            {
                const int pl  = tid >> 8;          // 0..1
                const int rem = tid & 255;
                const int row = rem >> 2, seg = rem & 3;
                const __half* sp = pl ? srcB3 : srcB1;
                const uint32_t dst = base + G13_AB + pl * G13_BB + row * 80 + seg * 16;
                CP_ASYNC16(dst, sp + (size_t)row * HH + k0 + seg * 8);
            }
            CP_COMMIT();
        };

        const int NC = HH / 32;   // 64
        load_chunk(0, 0);
        load_chunk(1, 1);

        for (int c = 0; c < NC; c++) {
            if (c == NC - 1) { CP_WAIT(0); } else { CP_WAIT(1); }
            __syncthreads();
            if (c + 2 < NC) load_chunk((c + 2) % 3, c + 2);

            const uint32_t aH = sb + (c % 3) * G13_BUF;
            const uint32_t bB = aH + G13_AB;
            #pragma unroll
            for (int kk = 0; kk < 2; kk++) {
                uint32_t ah[2][4];
                #pragma unroll
                for (int mt = 0; mt < 2; mt++) {
                    const uint32_t ao = (uint32_t)((m0w + mt * 16) * 80 + kk * 32) + aRowOff;
                    LDSM_X4(ah[mt][0], ah[mt][1], ah[mt][2], ah[mt][3], aH + ao);
                }
                #pragma unroll
                for (int np = 0; np < 2; np++) {
                    const uint32_t bo = (uint32_t)((n0w + np * 16) * 80 + kk * 32) + bRowOff;
                    uint32_t b1[4], b3[4];
                    LDSM_X4(b1[0], b1[1], b1[2], b1[3], bB + bo);
                    LDSM_X4(b3[0], b3[1], b3[2], b3[3], bB + G13_BB + bo);
                    #pragma unroll
                    for (int mt = 0; mt < 2; mt++)
                        #pragma unroll
                        for (int s = 0; s < 2; s++) {
                            const int nt = np * 2 + s;
                            mma16816(acc1[mt][nt], ah[mt], b1 + 2 * s);
                            mma16816(acc3[mt][nt], ah[mt], b3 + 2 * s);
                        }
                }
            }
        }

        // epilogue: silu(h1)*h3 -> fp16 -> smem stage (256 x 72 halves) -> store
        __syncthreads();
        char* st = smem;
        #pragma unroll
        for (int mt = 0; mt < 2; mt++)
            #pragma unroll
            for (int nt = 0; nt < 4; nt++) {
                const int gr = m0w + mt * 16 + (lane >> 2);
                const int cb = n0w + nt * 8 + 2 * (lane & 3);
                float a[4];
                #pragma unroll
                for (int j = 0; j < 4; j++) {
                    const float x = acc1[mt][nt][j];
                    a[j] = (x / (1.f + __expf(-x))) * acc3[mt][nt][j];
                }
                *(uint32_t*)(st + (gr * 72 + cb) * 2) =
                    pack2h(__float2half_rn(a[0]), __float2half_rn(a[1]));
                *(uint32_t*)(st + ((gr + 8) * 72 + cb) * 2) =
                    pack2h(__float2half_rn(a[2]), __float2half_rn(a[3]));
            }
        __syncthreads();
        #pragma unroll
        for (int it = 0; it < 4; it++) {
            const int idx = tid + it * 512;           // 0..2047
            const int row = idx >> 3, seg = idx & 7;
            if (m0b + row < cnt) {
                const size_t go = ((size_t)e * TT + m0b + row) * II + n0b + seg * 8;
                *(uint4*)(g_actf + go) = *(const uint4*)(st + (row * 72 + seg * 8) * 2);
            }
        }
    }

    // ---- fused w2 prepass tail: 8 transpose tiles per block (2048 blocks) ----
    {
        __syncthreads();
        __half* s = (__half*)smem;             // [32][66]
        const int tx = tid & 31, ty = tid >> 5;  // (32, 16)
        const int bl = blockIdx.x + 16 * (blockIdx.y + 8 * blockIdx.z);
        #pragma unroll
        for (int t = 0; t < 8; t++) {
            const int tile = bl * 8 + t;
            const int te   = tile >> 10;
            const int rem  = tile & 1023;
            const int h0   = (rem >> 4) * 32;
            const int i0   = (rem & 15) * 64;
            const float* src = w2 + (size_t)te * II * HH;
            #pragma unroll
            for (int j = 0; j < 4; j++) {
                const int i = ty + 16 * j;     // 0..63
                s[tx * 66 + i] = __float2half_rn(src[(size_t)(i0 + i) * HH + h0 + tx]);
            }
            __syncthreads();
            #pragma unroll
            for (int j = 0; j < 2; j++) {
                const int h = ty + 16 * j;     // 0..31
                const uint32_t v = *(const uint32_t*)&s[h * 66 + 2 * tx];
                *(uint32_t*)(g_w2f + ((size_t)te * HH + h0 + h) * II + i0 + 2 * tx) = v;
            }
            __syncthreads();
        }
    }
}

// ---------------- gemm2: 512thr, block 256m x 128n, warp 32x64 -----------------
#define G2_AB   (256 * STRIDE_H * 2)       // 20480
#define G2_BB   (128 * STRIDE_H * 2)       // 10240
#define G2_BUF  (G2_AB + G2_BB)            // 30720
#define G2_SMEM (3 * G2_BUF)               // 92160 (>= fp16 stage 256*136*2=69632)

__global__ __launch_bounds__(512, 1)
void gemm2_wm() {
    extern __shared__ char smem[];
    const int e    = blockIdx.z;
    const int cnt  = g_counts[e];
    const int m0b  = blockIdx.y * 256;
    if (m0b >= cnt) return;
    const int n0b  = blockIdx.x * 128;
    const int mrows = (cnt - m0b < 256) ? (cnt - m0b) : 256;

    const int tid  = threadIdx.x;
    const int wid  = tid >> 5, lane = tid & 31;
    const int m0w  = (wid & 7) * 32;       // 8 m-warps
    const int n0w  = (wid >> 3) * 64;      // 2 n-warps
    const uint32_t sb = smem_to_u32(smem);

    const __half* Af = g_actf + ((size_t)e * TT + m0b) * II;
    const __half* Bf = g_w2f + ((size_t)e * HH + n0b) * II;

    float acc[2][8][4];
    #pragma unroll
    for (int mt = 0; mt < 2; mt++)
        #pragma unroll
        for (int nt = 0; nt < 8; nt++)
            #pragma unroll
            for (int j = 0; j < 4; j++) acc[mt][nt][j] = 0.f;

    const uint32_t aRowOff = (uint32_t)((lane & 15) * 80 + ((lane >> 4) & 1) * 16);
    const uint32_t bRowOff = (uint32_t)((((lane >> 4) & 1) * 8 + (lane & 7)) * 80 +
                                        ((lane >> 3) & 1) * 16);

    auto load_chunk = [&](int buf, int c) {
        const int k0 = c * 32;
        const uint32_t base = sb + buf * G2_BUF;
        #pragma unroll
        for (int it = 0; it < 2; it++) {
            const int idx = tid + it * 512;
            const int row = idx >> 2, seg = idx & 3;    // 256 rows
            const uint32_t dst = base + row * 80 + seg * 16;
            const uint32_t ssz = (row < mrows) ? 16u : 0u;
            CP_ASYNC16Z(dst, Af + (size_t)row * II + k0 + seg * 8, ssz);
        }
        {
            const int row = tid >> 2, seg = tid & 3;    // 128 n-rows
            const uint32_t dst = base + G2_AB + row * 80 + seg * 16;
            CP_ASYNC16(dst, Bf + (size_t)row * II + k0 + seg * 8);
        }
        CP_COMMIT();
    };

    const int NC = II / 32;   // 32
    load_chunk(0, 0);
    load_chunk(1, 1);

    for (int c = 0; c < NC; c++) {
        if (c == NC - 1) { CP_WAIT(0); } else { CP_WAIT(1); }
        __syncthreads();
        if (c + 2 < NC) load_chunk((c + 2) % 3, c + 2);

        const uint32_t aH = sb + (c % 3) * G2_BUF;
        const uint32_t bB = aH + G2_AB;
        #pragma unroll
        for (int kk = 0; kk < 2; kk++) {
            uint32_t ah[2][4];
            #pragma unroll
            for (int mt = 0; mt < 2; mt++) {
                const uint32_t ao = (uint32_t)((m0w + mt * 16) * 80 + kk * 32) + aRowOff;
                LDSM_X4(ah[mt][0], ah[mt][1], ah[mt][2], ah[mt][3], aH + ao);
            }
            #pragma unroll
            for (int np = 0; np < 4; np++) {
                const uint32_t bo = (uint32_t)((n0w + np * 16) * 80 + kk * 32) + bRowOff;
                uint32_t bf[4];
                LDSM_X4(bf[0], bf[1], bf[2], bf[3], bB + bo);
                #pragma unroll
                for (int mt = 0; mt < 2; mt++)
                    #pragma unroll
                    for (int s = 0; s < 2; s++)
                        mma16816(acc[mt][np * 2 + s], ah[mt], &bf[np == np ? 2 * s : 0]);
            }
        }
    }

    // epilogue: fp16 stage (256 x 136 halves) -> coalesced fp16 store
    __syncthreads();
    char* st = smem;
    #pragma unroll
    for (int mt = 0; mt < 2; mt++)
        #pragma unroll
        for (int nt = 0; nt < 8; nt++) {
            const int gr = m0w + mt * 16 + (lane >> 2);
            const int cb = n0w + nt * 8 + 2 * (lane & 3);
            *(uint32_t*)(st + (gr * 136 + cb) * 2) =
                pack2h(__float2half_rn(acc[mt][nt][0]), __float2half_rn(acc[mt][nt][1]));
            *(uint32_t*)(st + ((gr + 8) * 136 + cb) * 2) =
                pack2h(__float2half_rn(acc[mt][nt][2]), __float2half_rn(acc[mt][nt][3]));
        }
    __syncthreads();
    #pragma unroll
    for (int it = 0; it < 8; it++) {
        const int idx = tid + it * 512;           // 0..4095
        const int row = idx >> 4, seg = idx & 15;
        if (row < mrows)
            *(uint4*)(g_h2h + ((size_t)e * TT + m0b + row) * HH + n0b + seg * 8) =
                *(const uint4*)(st + (row * 136 + seg * 8) * 2);
    }
}

// ---------------- combine ----------------
__global__ void combine_kernel(float* __restrict__ out) {
    const int t = blockIdx.y;
    const int h = blockIdx.x * blockDim.x + threadIdx.x;
    float s = 0.f;
    #pragma unroll
    for (int k = 0; k < TOPK; k++) {
        const int   fs = g_tslot[t * TOPK + k];
        const float w  = g_twt [t * TOPK + k];
        s += w * __half2float(g_h2h[(size_t)fs * HH + h]);
    }
    out[(size_t)t * HH + h] = s;
}

// ---------------- launch ----------------
extern "C" void kernel_launch(void* const* d_in, const int* in_sizes, int n_in,
                              void* d_out, int out_size) {
    const float* hs = (const float*)d_in[0];
    const float* gw = (const float*)d_in[1];
    const float* w1 = (const float*)d_in[2];
    const float* w3 = (const float*)d_in[3];
    const float* w2 = (const float*)d_in[4];
    float* out = (float*)d_out;

    cudaFuncSetAttribute(gemm13_wm, cudaFuncAttributeMaxDynamicSharedMemorySize, G13_SMEM);
    cudaFuncSetAttribute(gemm2_wm,  cudaFuncAttributeMaxDynamicSharedMemorySize, G2_SMEM);

    zero_counts_kernel<<<1, 32>>>();
    router_kernel<<<TT, 256>>>(hs, gw, w1, w3);
    gemm13_wm<<<dim3(II / 64, TT / 256, EE), 512, G13_SMEM>>>(w2);
    gemm2_wm <<<dim3(HH / 128, TT / 256, EE), 512, G2_SMEM>>>();
    combine_kernel<<<dim3(HH / 256, TT), 256>>>(out);
}

// round 16
// speedup vs baseline: 1.2464x; 1.2464x over previous
#include <cuda_runtime.h>
#include <cuda_fp16.h>
#include <cstdint>

#define TT   2048
#define HH   2048
#define II   1024
#define EE   16
#define TOPK 4

// ---------------- PTX helpers (sm_80-level only; target is plain sm_103) -------
__device__ __forceinline__ uint32_t smem_to_u32(const void* p) {
    uint32_t a;
    asm("{ .reg .u64 t; cvta.to.shared.u64 t, %1; cvt.u32.u64 %0, t; }"
        : "=r"(a) : "l"(p));
    return a;
}
#define CP_ASYNC16(dst, src) \
    asm volatile("cp.async.cg.shared.global [%0], [%1], 16;" :: "r"(dst), "l"(src) : "memory")
#define CP_ASYNC16Z(dst, src, ssz) \
    asm volatile("cp.async.cg.shared.global [%0], [%1], 16, %2;" :: "r"(dst), "l"(src), "r"(ssz) : "memory")
#define CP_COMMIT()  asm volatile("cp.async.commit_group;" ::: "memory")
#define CP_WAIT(n)   asm volatile("cp.async.wait_group %0;" :: "n"(n) : "memory")

#define LDSM_X4(r0, r1, r2, r3, addr) \
    asm volatile("ldmatrix.sync.aligned.m8n8.x4.shared.b16 {%0,%1,%2,%3}, [%4];" \
                 : "=r"(r0), "=r"(r1), "=r"(r2), "=r"(r3) : "r"(addr))

// D += A*B  (m16n8k16, fp16 in, f32 accum)
__device__ __forceinline__ void mma16816(float* c, const uint32_t* a, const uint32_t* b) {
    asm volatile(
        "mma.sync.aligned.m16n8k16.row.col.f32.f16.f16.f32 "
        "{%0,%1,%2,%3}, {%4,%5,%6,%7}, {%8,%9}, {%0,%1,%2,%3};"
        : "+f"(c[0]), "+f"(c[1]), "+f"(c[2]), "+f"(c[3])
        : "r"(a[0]), "r"(a[1]), "r"(a[2]), "r"(a[3]), "r"(b[0]), "r"(b[1]));
}

// ---------------- scratch ----------------
__device__ int   g_counts[EE];
__device__ int   g_tok[EE * TT];
__device__ int   g_tslot[TT * TOPK];
__device__ float g_twt[TT * TOPK];
__device__ __half g_h2h [(size_t)EE * TT * HH];       // down-proj result fp16
__device__ __half g_hsf [(size_t)TT * HH];            // hs fp16
__device__ __half g_actf[(size_t)EE * TT * II];       // act fp16
__device__ __half g_w13f[(size_t)EE * 2 * II * HH];   // [e*2+mat][i][h] fp16
__device__ __half g_w2f [(size_t)EE * HH * II];       // [e][h][i] fp16

__device__ __forceinline__ uint32_t pack2h(__half a, __half b) {
    return (uint32_t)__half_as_ushort(a) | ((uint32_t)__half_as_ushort(b) << 16);
}

// ---------------- router (+ fused hs->fp16 conversion) ----------------
__global__ void zero_counts_kernel() {
    if (threadIdx.x < EE) g_counts[threadIdx.x] = 0;
}

__global__ void router_kernel(const float* __restrict__ hs,
                              const float* __restrict__ gw) {
    const int t = blockIdx.x;
    __shared__ float xs[HH];
    __shared__ float logits[EE];
    const float* x = hs + (size_t)t * HH;
    for (int i = threadIdx.x; i < HH; i += blockDim.x) xs[i] = x[i];
    __syncthreads();
    // fused: write fp16 copy of this row (coalesced uint32 stores)
    {
        uint32_t* dst = (uint32_t*)(g_hsf + (size_t)t * HH);
        for (int i = threadIdx.x; i < HH / 2; i += blockDim.x)
            dst[i] = pack2h(__float2half_rn(xs[2 * i]), __float2half_rn(xs[2 * i + 1]));
    }
    const int warp = threadIdx.x >> 5, lane = threadIdx.x & 31;
    for (int e = warp; e < EE; e += 8) {
        const float* g = gw + (size_t)e * HH;
        float s = 0.f;
        for (int k = lane; k < HH; k += 32) s += xs[k] * g[k];
        #pragma unroll
        for (int o = 16; o; o >>= 1) s += __shfl_xor_sync(0xffffffffu, s, o);
        if (lane == 0) logits[e] = s;
    }
    __syncthreads();
    if (threadIdx.x == 0) {
        float lv[EE];
        #pragma unroll
        for (int e = 0; e < EE; e++) lv[e] = logits[e];
        int idx[TOPK]; float val[TOPK];
        #pragma unroll
        for (int k = 0; k < TOPK; k++) {
            float best = -1e30f; int bi = 0;
            for (int e = 0; e < EE; e++) if (lv[e] > best) { best = lv[e]; bi = e; }
            idx[k] = bi; val[k] = best; lv[bi] = -1e30f;
        }
        const float m = val[0];
        float w[TOPK], se = 0.f;
        #pragma unroll
        for (int k = 0; k < TOPK; k++) { w[k] = __expf(val[k] - m); se += w[k]; }
        const float inv = 1.f / se;
        #pragma unroll
        for (int k = 0; k < TOPK; k++) {
            const int e = idx[k];
            const int slot = atomicAdd(&g_counts[e], 1);
            g_tok[e * TT + slot]  = t;
            g_tslot[t * TOPK + k] = e * TT + slot;
            g_twt[t * TOPK + k]   = w[k] * inv;
        }
    }
}

// ---------------- prepass: transpose w1/w3 to fp16 (coalesced writes) ----------
__global__ void prep_w13_kernel(const float* __restrict__ w1,
                                const float* __restrict__ w3) {
    __shared__ __half s[32][66];           // [i][h], 33-word rows: conflict-free
    const int z = blockIdx.z;              // e*2+mat
    const int e = z >> 1, mat = z & 1;
    const float* src = (mat ? w3 : w1) + (size_t)e * HH * II;
    const int i0 = blockIdx.x * 32, h0 = blockIdx.y * 64;
    const int tx = threadIdx.x, ty = threadIdx.y;
    #pragma unroll
    for (int j = 0; j < 8; j++) {
        const int h = ty + 8 * j;          // 0..63
        s[tx][h] = __float2half_rn(src[(size_t)(h0 + h) * II + i0 + tx]);
    }
    __syncthreads();
    #pragma unroll
    for (int j = 0; j < 4; j++) {
        const int i = ty + 8 * j;          // 0..31
        const uint32_t v = *(const uint32_t*)&s[i][2 * tx];
        *(uint32_t*)(g_w13f + ((size_t)z * II + i0 + i) * HH + h0 + 2 * tx) = v;
    }
}

// ---------------- gemm13: fp16 HMMA, 3-stage pipeline, + fused w2 prep tail ----
#define STRIDE_H 40                        // halves per smem row (80B)
#define G13_AB   (128 * STRIDE_H * 2)      // 10240 A plane
#define G13_BB   (64 * STRIDE_H * 2)       // 5120 per B plane
#define G13_BUF  (G13_AB + 2 * G13_BB)     // 20480 per buffer
#define G13_SMEM (3 * G13_BUF + 1024)

__global__ __launch_bounds__(256, 2)
void gemm13_wm(const float* __restrict__ w2) {
    extern __shared__ char smem[];
    const int e    = blockIdx.z;
    const int cnt  = g_counts[e];
    const int m0b  = blockIdx.y * 128;
    const int n0b  = blockIdx.x * 64;

    const int tid  = threadIdx.x;
    const int wid  = tid >> 5, lane = tid & 31;
    const int m0w  = (wid & 3) * 32;
    const int n0w  = (wid >> 2) * 32;
    const uint32_t sb = smem_to_u32(smem);

    if (m0b < cnt) {
        int* rowTokS = (int*)(smem + 3 * G13_BUF);
        if (tid < 128) rowTokS[tid] = (m0b + tid < cnt) ? g_tok[e * TT + m0b + tid] : -1;
        __syncthreads();

        const __half* srcB1 = g_w13f + ((size_t)(e * 2 + 0) * II + n0b) * HH;
        const __half* srcB3 = g_w13f + ((size_t)(e * 2 + 1) * II + n0b) * HH;

        float acc1[2][4][4], acc3[2][4][4];
        #pragma unroll
        for (int mt = 0; mt < 2; mt++)
            #pragma unroll
            for (int nt = 0; nt < 4; nt++)
                #pragma unroll
                for (int j = 0; j < 4; j++) { acc1[mt][nt][j] = 0.f; acc3[mt][nt][j] = 0.f; }

        const uint32_t aRowOff = (uint32_t)((lane & 15) * 80 + ((lane >> 4) & 1) * 16);
        const uint32_t bRowOff = (uint32_t)((((lane >> 4) & 1) * 8 + (lane & 7)) * 80 +
                                            ((lane >> 3) & 1) * 16);

        auto load_chunk = [&](int buf, int c) {
            const int k0 = c * 32;
            const uint32_t base = sb + buf * G13_BUF;
            #pragma unroll
            for (int it = 0; it < 2; it++) {
                const int idx = tid + it * 256;
                const int row = idx >> 2, seg = idx & 3;
                const int tok = rowTokS[row];
                const uint32_t dst = base + row * 80 + seg * 16;
                const __half* s =
                    (tok >= 0 ? g_hsf + (size_t)tok * HH : g_hsf) + k0 + seg * 8;
                const uint32_t ssz = (tok >= 0) ? 16u : 0u;
                CP_ASYNC16Z(dst, s, ssz);
            }
            {
                const int row = tid >> 2, seg = tid & 3;
                const uint32_t dst1 = base + G13_AB + row * 80 + seg * 16;
                const uint32_t dst3 = dst1 + G13_BB;
                CP_ASYNC16(dst1, srcB1 + (size_t)row * HH + k0 + seg * 8);
                CP_ASYNC16(dst3, srcB3 + (size_t)row * HH + k0 + seg * 8);
            }
            CP_COMMIT();
        };

        const int NC = HH / 32;   // 64
        load_chunk(0, 0);
        load_chunk(1, 1);

        for (int c = 0; c < NC; c++) {
            if (c == NC - 1) { CP_WAIT(0); } else { CP_WAIT(1); }
            __syncthreads();
            if (c + 2 < NC) load_chunk((c + 2) % 3, c + 2);

            const uint32_t aH = sb + (c % 3) * G13_BUF;
            const uint32_t bB = aH + G13_AB;
            #pragma unroll
            for (int kk = 0; kk < 2; kk++) {
                uint32_t ah[2][4];
                #pragma unroll
                for (int mt = 0; mt < 2; mt++) {
                    const uint32_t ao = (uint32_t)((m0w + mt * 16) * 80 + kk * 32) + aRowOff;
                    LDSM_X4(ah[mt][0], ah[mt][1], ah[mt][2], ah[mt][3], aH + ao);
                }
                #pragma unroll
                for (int np = 0; np < 2; np++) {
                    const uint32_t bo = (uint32_t)((n0w + np * 16) * 80 + kk * 32) + bRowOff;
                    uint32_t b1[4], b3[4];
                    LDSM_X4(b1[0], b1[1], b1[2], b1[3], bB + bo);
                    LDSM_X4(b3[0], b3[1], b3[2], b3[3], bB + G13_BB + bo);
                    #pragma unroll
                    for (int mt = 0; mt < 2; mt++)
                        #pragma unroll
                        for (int s = 0; s < 2; s++) {
                            const int nt = np * 2 + s;
                            mma16816(acc1[mt][nt], ah[mt], b1 + 2 * s);
                            mma16816(acc3[mt][nt], ah[mt], b3 + 2 * s);
                        }
                }
            }
        }

        // epilogue: silu(h1)*h3 -> fp16 -> smem stage -> coalesced store
        __syncthreads();
        char* st = smem;                       // 128 x 72 halves
        #pragma unroll
        for (int mt = 0; mt < 2; mt++)
            #pragma unroll
            for (int nt = 0; nt < 4; nt++) {
                const int gr = m0w + mt * 16 + (lane >> 2);
                const int cb = n0w + nt * 8 + 2 * (lane & 3);
                float a[4];
                #pragma unroll
                for (int j = 0; j < 4; j++) {
                    const float x = acc1[mt][nt][j];
                    a[j] = (x / (1.f + __expf(-x))) * acc3[mt][nt][j];
                }
                *(uint32_t*)(st + (gr * 72 + cb) * 2) =
                    pack2h(__float2half_rn(a[0]), __float2half_rn(a[1]));
                *(uint32_t*)(st + ((gr + 8) * 72 + cb) * 2) =
                    pack2h(__float2half_rn(a[2]), __float2half_rn(a[3]));
            }
        __syncthreads();
        #pragma unroll
        for (int it = 0; it < 4; it++) {
            const int idx = tid + it * 256;           // 0..1023
            const int row = idx >> 3, seg = idx & 7;
            if (m0b + row < cnt) {
                const size_t go = ((size_t)e * TT + m0b + row) * II + n0b + seg * 8;
                *(uint4*)(g_actf + go) = *(const uint4*)(st + (row * 72 + seg * 8) * 2);
            }
        }
    }

    // ---- fused w2 prepass tail: this block converts 4 transpose tiles ----
    {
        __syncthreads();
        __half* s = (__half*)smem;             // [32][66]
        const int tx = tid & 31, ty = tid >> 5;  // (32, 8)
        const int bl = blockIdx.x + 16 * (blockIdx.y + 16 * blockIdx.z);
        #pragma unroll
        for (int t = 0; t < 4; t++) {
            const int tile = bl * 4 + t;
            const int te   = tile >> 10;       // 1024 tiles per expert
            const int rem  = tile & 1023;
            const int h0   = (rem >> 4) * 32;
            const int i0   = (rem & 15) * 64;
            const float* src = w2 + (size_t)te * II * HH;
            #pragma unroll
            for (int j = 0; j < 8; j++) {
                const int i = ty + 8 * j;      // 0..63
                s[tx * 66 + i] = __float2half_rn(src[(size_t)(i0 + i) * HH + h0 + tx]);
            }
            __syncthreads();
            #pragma unroll
            for (int j = 0; j < 4; j++) {
                const int h = ty + 8 * j;      // 0..31
                const uint32_t v = *(const uint32_t*)&s[h * 66 + 2 * tx];
                *(uint32_t*)(g_w2f + ((size_t)te * HH + h0 + h) * II + i0 + 2 * tx) = v;
            }
            __syncthreads();
        }
    }
}

// ---------------- gemm2: 128x128 block, warp 32x64, 3-stage, 1 sync/chunk ------
#define G2_AB   (128 * STRIDE_H * 2)       // 10240
#define G2_BB   (128 * STRIDE_H * 2)       // 10240 (128 n-rows x 32k)
#define G2_BUF  (G2_AB + G2_BB)            // 20480
#define G2_SMEM (3 * G2_BUF)               // 61440 (>= fp16 stage 34816)

__global__ __launch_bounds__(256, 2)
void gemm2_wm() {
    extern __shared__ char smem[];
    const int e    = blockIdx.z;
    const int cnt  = g_counts[e];
    const int m0b  = blockIdx.y * 128;
    if (m0b >= cnt) return;
    const int n0b  = blockIdx.x * 128;
    const int mrows = (cnt - m0b < 128) ? (cnt - m0b) : 128;

    const int tid  = threadIdx.x;
    const int wid  = tid >> 5, lane = tid & 31;
    const int m0w  = (wid & 3) * 32;
    const int n0w  = (wid >> 2) * 64;
    const uint32_t sb = smem_to_u32(smem);

    const __half* Af = g_actf + ((size_t)e * TT + m0b) * II;
    const __half* Bf = g_w2f + ((size_t)e * HH + n0b) * II;

    float acc[2][8][4];
    #pragma unroll
    for (int mt = 0; mt < 2; mt++)
        #pragma unroll
        for (int nt = 0; nt < 8; nt++)
            #pragma unroll
            for (int j = 0; j < 4; j++) acc[mt][nt][j] = 0.f;

    const uint32_t aRowOff = (uint32_t)((lane & 15) * 80 + ((lane >> 4) & 1) * 16);
    const uint32_t bRowOff = (uint32_t)((((lane >> 4) & 1) * 8 + (lane & 7)) * 80 +
                                        ((lane >> 3) & 1) * 16);

    auto load_chunk = [&](int buf, int c) {
        const int k0 = c * 32;
        const uint32_t base = sb + buf * G2_BUF;
        #pragma unroll
        for (int it = 0; it < 2; it++) {
            const int idx = tid + it * 256;
            const int row = idx >> 2, seg = idx & 3;
            const uint32_t dst = base + row * 80 + seg * 16;
            const uint32_t ssz = (row < mrows) ? 16u : 0u;
            CP_ASYNC16Z(dst, Af + (size_t)row * II + k0 + seg * 8, ssz);
        }
        #pragma unroll
        for (int it = 0; it < 2; it++) {
            const int idx = tid + it * 256;
            const int row = idx >> 2, seg = idx & 3;     // 128 n-rows x 32k
            const uint32_t dst = base + G2_AB + row * 80 + seg * 16;
            CP_ASYNC16(dst, Bf + (size_t)row * II + k0 + seg * 8);
        }
        CP_COMMIT();
    };

    const int NC = II / 32;   // 32
    load_chunk(0, 0);
    load_chunk(1, 1);

    for (int c = 0; c < NC; c++) {
        if (c == NC - 1) { CP_WAIT(0); } else { CP_WAIT(1); }
        __syncthreads();
        if (c + 2 < NC) load_chunk((c + 2) % 3, c + 2);

        const uint32_t aH = sb + (c % 3) * G2_BUF;
        const uint32_t bB = aH + G2_AB;
        #pragma unroll
        for (int kk = 0; kk < 2; kk++) {
            uint32_t ah[2][4];
            #pragma unroll
            for (int mt = 0; mt < 2; mt++) {
                const uint32_t ao = (uint32_t)((m0w + mt * 16) * 80 + kk * 32) + aRowOff;
                LDSM_X4(ah[mt][0], ah[mt][1], ah[mt][2], ah[mt][3], aH + ao);
            }
            #pragma unroll
            for (int np = 0; np < 4; np++) {
                const uint32_t bo = (uint32_t)((n0w + np * 16) * 80 + kk * 32) + bRowOff;
                uint32_t bf[4];
                LDSM_X4(bf[0], bf[1], bf[2], bf[3], bB + bo);
                #pragma unroll
                for (int mt = 0; mt < 2; mt++)
                    #pragma unroll
                    for (int s = 0; s < 2; s++)
                        mma16816(acc[mt][np * 2 + s], ah[mt], bf + 2 * s);
            }
        }
    }

    // epilogue: fp16 stage (128 x 136 halves) -> coalesced fp16 store
    __syncthreads();
    char* st = smem;
    #pragma unroll
    for (int mt = 0; mt < 2; mt++)
        #pragma unroll
        for (int nt = 0; nt < 8; nt++) {
            const int gr = m0w + mt * 16 + (lane >> 2);
            const int cb = n0w + nt * 8 + 2 * (lane & 3);
            *(uint32_t*)(st + (gr * 136 + cb) * 2) =
                pack2h(__float2half_rn(acc[mt][nt][0]), __float2half_rn(acc[mt][nt][1]));
            *(uint32_t*)(st + ((gr + 8) * 136 + cb) * 2) =
                pack2h(__float2half_rn(acc[mt][nt][2]), __float2half_rn(acc[mt][nt][3]));
        }
    __syncthreads();
    #pragma unroll
    for (int it = 0; it < 8; it++) {
        const int idx = tid + it * 256;           // 0..2047
        const int row = idx >> 4, seg = idx & 15;
        if (row < mrows)
            *(uint4*)(g_h2h + ((size_t)e * TT + m0b + row) * HH + n0b + seg * 8) =
                *(const uint4*)(st + (row * 136 + seg * 8) * 2);
    }
}

// ---------------- combine (vectorized: 4 h per thread) ----------------
__global__ void combine_kernel(float* __restrict__ out) {
    const int t  = blockIdx.y;
    const int h4 = (blockIdx.x * blockDim.x + threadIdx.x) * 4;
    float s0 = 0.f, s1 = 0.f, s2 = 0.f, s3 = 0.f;
    #pragma unroll
    for (int k = 0; k < TOPK; k++) {
        const int   fs = g_tslot[t * TOPK + k];
        const float w  = g_twt [t * TOPK + k];
        const uint2 v  = *(const uint2*)(g_h2h + (size_t)fs * HH + h4);
        const __half2 p0 = *(const __half2*)&v.x;
        const __half2 p1 = *(const __half2*)&v.y;
        s0 += w * __half2float(__low2half(p0));
        s1 += w * __half2float(__high2half(p0));
        s2 += w * __half2float(__low2half(p1));
        s3 += w * __half2float(__high2half(p1));
    }
    *(float4*)(out + (size_t)t * HH + h4) = make_float4(s0, s1, s2, s3);
}

// ---------------- launch ----------------
extern "C" void kernel_launch(void* const* d_in, const int* in_sizes, int n_in,
                              void* d_out, int out_size) {
    const float* hs = (const float*)d_in[0];
    const float* gw = (const float*)d_in[1];
    const float* w1 = (const float*)d_in[2];
    const float* w3 = (const float*)d_in[3];
    const float* w2 = (const float*)d_in[4];
    float* out = (float*)d_out;

    cudaFuncSetAttribute(gemm13_wm, cudaFuncAttributeMaxDynamicSharedMemorySize, G13_SMEM);
    cudaFuncSetAttribute(gemm2_wm,  cudaFuncAttributeMaxDynamicSharedMemorySize, G2_SMEM);

    zero_counts_kernel<<<1, 32>>>();
    router_kernel<<<TT, 256>>>(hs, gw);
    prep_w13_kernel<<<dim3(II / 32, HH / 64, EE * 2), dim3(32, 8)>>>(w1, w3);
    gemm13_wm<<<dim3(II / 64, TT / 128, EE), 256, G13_SMEM>>>(w2);
    gemm2_wm <<<dim3(HH / 128, TT / 128, EE), 256, G2_SMEM>>>();
    combine_kernel<<<dim3(HH / 4 / 256, TT), 256>>>(out);
}